// round 12
// baseline (speedup 1.0000x reference)
#include <cuda_runtime.h>
#include <cuda_bf16.h>
#include <math.h>
#include <stdint.h>

// Problem constants (fixed shapes)
#define T_TOK 4096
#define DIM   512
#define FDIM  1024
#define NE    8
#define TOPK  2
#define NPAIR (T_TOK*TOPK)

// ---------------- device scratch (static; no runtime allocation) ----------------
__device__ int   g_cnt[NE];
__device__ int   g_list[NE*T_TOK];   // packed (token<<1)|k
__device__ float g_wgt [NE*T_TOK];
__device__ float g_sumP[NE];
__device__ float g_zsum;

// bf16 hi/lo splits (NATURAL layouts — no transpose)
__device__ __nv_bfloat16 g_xh[(size_t)T_TOK*DIM];
__device__ __nv_bfloat16 g_xl[(size_t)T_TOK*DIM];
__device__ __nv_bfloat16 g_gh[(size_t)NE*DIM*FDIM];  // gate [E][D][F]
__device__ __nv_bfloat16 g_gl[(size_t)NE*DIM*FDIM];
__device__ __nv_bfloat16 g_uh[(size_t)NE*DIM*FDIM];  // up   [E][D][F]
__device__ __nv_bfloat16 g_ul[(size_t)NE*DIM*FDIM];
__device__ __nv_bfloat16 g_dh[(size_t)NE*FDIM*DIM];  // down [E][F][D]
__device__ __nv_bfloat16 g_dl[(size_t)NE*FDIM*DIM];
__device__ __nv_bfloat16 g_hh[(size_t)NPAIR*FDIM];   // hidden hi
__device__ __nv_bfloat16 g_hl[(size_t)NPAIR*FDIM];   // hidden lo
__device__ float g_pout[(size_t)NPAIR*DIM];

// ================= PTX helpers (family-portable: sm_80+) =================
__device__ __forceinline__ uint32_t smem_u32(const void* p) {
    uint32_t a;
    asm("{ .reg .u64 t; cvta.to.shared.u64 t, %1; cvt.u32.u64 %0, t; }" : "=r"(a) : "l"(p));
    return a;
}
__device__ __forceinline__ void cp16(uint32_t dst, const void* src, uint32_t bytes) {
    asm volatile("cp.async.cg.shared.global [%0], [%1], 16, %2;"
                 :: "r"(dst), "l"(src), "r"(bytes) : "memory");
}
#define CP_COMMIT() asm volatile("cp.async.commit_group;" ::: "memory")
#define CP_WAITG(n) asm volatile("cp.async.wait_group %0;" :: "n"(n) : "memory")

__device__ __forceinline__ void ldsm_x4(uint32_t* r, uint32_t addr) {
    asm volatile("ldmatrix.sync.aligned.m8n8.x4.shared.b16 {%0,%1,%2,%3}, [%4];"
        : "=r"(r[0]), "=r"(r[1]), "=r"(r[2]), "=r"(r[3]) : "r"(addr));
}
__device__ __forceinline__ void ldsm_x4_t(uint32_t* r, uint32_t addr) {
    asm volatile("ldmatrix.sync.aligned.m8n8.x4.trans.shared.b16 {%0,%1,%2,%3}, [%4];"
        : "=r"(r[0]), "=r"(r[1]), "=r"(r[2]), "=r"(r[3]) : "r"(addr));
}
__device__ __forceinline__ void mma_bf16(float* d, const uint32_t* a, const uint32_t* b) {
    asm volatile("mma.sync.aligned.m16n8k16.row.col.f32.bf16.bf16.f32 "
        "{%0,%1,%2,%3}, {%4,%5,%6,%7}, {%8,%9}, {%0,%1,%2,%3};"
        : "+f"(d[0]), "+f"(d[1]), "+f"(d[2]), "+f"(d[3])
        : "r"(a[0]), "r"(a[1]), "r"(a[2]), "r"(a[3]), "r"(b[0]), "r"(b[1]));
}

__device__ __forceinline__ void split_bf16(float v, __nv_bfloat16& h, __nv_bfloat16& l) {
    h = __float2bfloat16(v);
    l = __float2bfloat16(v - __bfloat162float(h));
}

// ---------------- prep: zero accumulators + split x + split weights (one launch) ----------------
#define XN4  (T_TOK*DIM/4)          // 524288
#define WPER (NE*DIM*FDIM/4)        // 1048576 float4s per weight tensor
#define PREP_TOT (XN4 + 3*WPER)

__global__ void prep_kernel(const float* __restrict__ x,
                            const float* __restrict__ gw,
                            const float* __restrict__ uw,
                            const float* __restrict__ dw) {
    int i = blockIdx.x * blockDim.x + threadIdx.x;
    if (i < NE + 1) {
        if (i < NE) { g_cnt[i] = 0; g_sumP[i] = 0.f; }
        else        g_zsum = 0.f;
    }
    if (i >= PREP_TOT) return;

    const float* src;
    __nv_bfloat16 *oh, *ol;
    size_t j;
    if (i < XN4) { src = x; oh = g_xh; ol = g_xl; j = i; }
    else {
        int k = i - XN4;
        int which = k / WPER;
        j = k - which * WPER;
        src = (which == 0) ? gw : (which == 1) ? uw : dw;
        oh  = (which == 0) ? g_gh : (which == 1) ? g_uh : g_dh;
        ol  = (which == 0) ? g_gl : (which == 1) ? g_ul : g_dl;
    }
    float4 v = ((const float4*)src)[j];
    __nv_bfloat16 h0,h1,h2,h3,l0,l1,l2,l3;
    split_bf16(v.x,h0,l0); split_bf16(v.y,h1,l1);
    split_bf16(v.z,h2,l2); split_bf16(v.w,h3,l3);
    ((__nv_bfloat162*)oh)[2*j]   = __nv_bfloat162(h0,h1);
    ((__nv_bfloat162*)oh)[2*j+1] = __nv_bfloat162(h2,h3);
    ((__nv_bfloat162*)ol)[2*j]   = __nv_bfloat162(l0,l1);
    ((__nv_bfloat162*)ol)[2*j+1] = __nv_bfloat162(l2,l3);
}

// ---------------- router: warp-per-token (coalesced), block-aggregated atomics ----------------
#define RT_TOK 32
__global__ void __launch_bounds__(1024) router_kernel(const float* __restrict__ x,
                                                      const float* __restrict__ rw) {
    __shared__ float s_sumP[NE];
    __shared__ float s_zsum;
    __shared__ int   s_cnt[NE];
    __shared__ int   s_base[NE];
    __shared__ int   s_ebuf[NE][2*RT_TOK];
    __shared__ float s_wbuf[NE][2*RT_TOK];

    int tid  = threadIdx.x;
    int wrp  = tid >> 5;
    int lane = tid & 31;
    int tok  = blockIdx.x * RT_TOK + wrp;

    if (tid < NE) { s_sumP[tid] = 0.f; s_cnt[tid] = 0; }
    if (tid == NE) s_zsum = 0.f;
    __syncthreads();

    const float4* xp = (const float4*)(x + (size_t)tok * DIM);
    float4 xv[4];
#pragma unroll
    for (int i = 0; i < 4; i++) xv[i] = xp[lane * 4 + i];

    float logit[NE];
#pragma unroll
    for (int e = 0; e < NE; e++) {
        const float4* wp = (const float4*)(rw + (size_t)e * DIM);
        float acc = 0.f;
#pragma unroll
        for (int i = 0; i < 4; i++) {
            float4 w4 = wp[lane * 4 + i];
            acc += xv[i].x * w4.x + xv[i].y * w4.y + xv[i].z * w4.z + xv[i].w * w4.w;
        }
#pragma unroll
        for (int o = 16; o > 0; o >>= 1) acc += __shfl_xor_sync(0xffffffffu, acc, o);
        logit[e] = acc;
    }

    if (lane == 0) {
        float m = logit[0];
#pragma unroll
        for (int e = 1; e < NE; e++) m = fmaxf(m, logit[e]);
        float p[NE]; float se = 0.f;
#pragma unroll
        for (int e = 0; e < NE; e++) { p[e] = expf(logit[e] - m); se += p[e]; }
        float inv = 1.f / se;

        int i0 = 0; float v0 = -1.f;
#pragma unroll
        for (int e = 0; e < NE; e++) if (p[e] > v0) { v0 = p[e]; i0 = e; }
        int i1 = -1; float v1 = -1.f;
#pragma unroll
        for (int e = 0; e < NE; e++) if (e != i0 && p[e] > v1) { v1 = p[e]; i1 = e; }

        float s2 = v0 + v1;
        float w0 = v0 / s2, w1 = v1 / s2;

        int p0 = atomicAdd(&s_cnt[i0], 1);
        s_ebuf[i0][p0] = (tok << 1);
        s_wbuf[i0][p0] = w0;
        int p1 = atomicAdd(&s_cnt[i1], 1);
        s_ebuf[i1][p1] = (tok << 1) | 1;
        s_wbuf[i1][p1] = w1;

#pragma unroll
        for (int e = 0; e < NE; e++) atomicAdd(&s_sumP[e], p[e] * inv);
        float lse = m + logf(se);
        atomicAdd(&s_zsum, lse * lse);
    }
    __syncthreads();

    if (tid < NE) {
        s_base[tid] = atomicAdd(&g_cnt[tid], s_cnt[tid]);
        atomicAdd(&g_sumP[tid], s_sumP[tid]);
    }
    if (tid == NE) atomicAdd(&g_zsum, s_zsum);
    __syncthreads();

    if (wrp < NE * 4) {
        int e = wrp >> 2, q = wrp & 3;
        int c = s_cnt[e], b = s_base[e];
        for (int i = q * 32 + lane; i < c; i += 128) {
            g_list[e * T_TOK + b + i] = s_ebuf[e][i];
            g_wgt [e * T_TOK + b + i] = s_wbuf[e][i];
        }
    }
}

// ================= Phase A: gate/up warp-MMA GEMM (unchanged from R11) =================
#define GU_STG  55296
#define GU_SMEM (1024 + 2*GU_STG)

__global__ void __launch_bounds__(256, 2) gateup_mma_kernel() {
    extern __shared__ char smem[];
    uint32_t sb = smem_u32(smem);
    int e = blockIdx.z;
    int cnt = g_cnt[e];
    int row0 = blockIdx.y * 64;
    if (row0 >= cnt) return;
    int col0 = blockIdx.x * 64;
    int tid = threadIdx.x, wid = tid >> 5, lid = tid & 31;
    int wm = wid >> 2, wn = wid & 3;
    int g = lid >> 2, t2 = (lid & 3) * 2;
    int* sTok = (int*)smem;

    for (int i = tid; i < 64; i += 256) {
        int r = row0 + i;
        sTok[i] = (r < cnt) ? g_list[e * T_TOK + r] : -1;
    }
    __syncthreads();

    const __nv_bfloat16* b0 = g_gh + (size_t)e * DIM * FDIM;
    const __nv_bfloat16* b1 = g_gl + (size_t)e * DIM * FDIM;
    const __nv_bfloat16* b2 = g_uh + (size_t)e * DIM * FDIM;
    const __nv_bfloat16* b3 = g_ul + (size_t)e * DIM * FDIM;

    float accg[2][2][4] = {}, accu[2][2][4] = {};

    auto stage = [&](int chunk) {
        int kt = chunk * 64;
        uint32_t bb = sb + 1024 + (uint32_t)(chunk & 1) * GU_STG;
#pragma unroll
        for (int it = 0; it < 4; it++) {
            int t = tid + it * 256;
            int arr = t >> 9, u = t & 511, row = u >> 3, seg = u & 7;
            int entry = sTok[row];
            uint32_t bytes = (entry >= 0) ? 16u : 0u;
            const __nv_bfloat16* src = (arr ? g_xl : g_xh)
                + (size_t)((entry >= 0) ? (entry >> 1) : 0) * DIM + kt + seg * 8;
            cp16(bb + arr * 9216 + row * 144 + seg * 16, src, bytes);
        }
#pragma unroll
        for (int it = 0; it < 8; it++) {
            int t = tid + it * 256;
            int arr = t >> 9, u = t & 511, row = u >> 3, seg = u & 7;
            const __nv_bfloat16* src = (arr == 0) ? b0 : (arr == 1) ? b1 : (arr == 2) ? b2 : b3;
            cp16(bb + 18432 + arr * 9216 + row * 144 + seg * 16,
                 src + (size_t)(kt + row) * FDIM + col0 + seg * 8, 16u);
        }
    };

    uint32_t laneO = (uint32_t)(((lid & 7) + ((lid >> 3) & 1) * 8) * 144 + ((lid >> 4) & 1) * 16);

    stage(0); CP_COMMIT();
    for (int c = 0; c < 8; c++) {
        if (c + 1 < 8) { stage(c + 1); CP_COMMIT(); CP_WAITG(1); }
        else           { CP_WAITG(0); }
        __syncthreads();
        uint32_t bb = sb + 1024 + (uint32_t)(c & 1) * GU_STG;
        uint32_t aBase = bb + (uint32_t)(wm * 32) * 144 + laneO;
        uint32_t bBase = bb + 18432 + laneO + (uint32_t)(wn * 16) * 2;
#pragma unroll
        for (int kk = 0; kk < 4; kk++) {
            uint32_t ah[2][4], al[2][4];
#pragma unroll
            for (int mt = 0; mt < 2; mt++) {
                uint32_t aa = aBase + mt * (16 * 144) + kk * 32;
                ldsm_x4(ah[mt], aa);
                ldsm_x4(al[mt], aa + 9216);
            }
            uint32_t ba = bBase + kk * (16 * 144);
            uint32_t bgh[4], bgl[4], buh[4], bul[4];
            ldsm_x4_t(bgh, ba);
            ldsm_x4_t(bgl, ba + 9216);
            ldsm_x4_t(buh, ba + 18432);
            ldsm_x4_t(bul, ba + 27648);
#pragma unroll
            for (int h = 0; h < 2; h++) {
#pragma unroll
                for (int mt = 0; mt < 2; mt++) {
                    mma_bf16(accg[mt][h], ah[mt], bgh + h * 2);
                    mma_bf16(accg[mt][h], ah[mt], bgl + h * 2);
                    mma_bf16(accg[mt][h], al[mt], bgh + h * 2);
                    mma_bf16(accu[mt][h], ah[mt], buh + h * 2);
                    mma_bf16(accu[mt][h], ah[mt], bul + h * 2);
                    mma_bf16(accu[mt][h], al[mt], buh + h * 2);
                }
            }
        }
        __syncthreads();
    }

#pragma unroll
    for (int mt = 0; mt < 2; mt++) {
        int r0 = wm * 32 + mt * 16 + g;
        int e0 = sTok[r0], e1 = sTok[r0 + 8];
#pragma unroll
        for (int h = 0; h < 2; h++) {
            int colg = col0 + wn * 16 + h * 8 + t2;
            const float* dg = accg[mt][h];
            const float* du = accu[mt][h];
            if (e0 >= 0) {
                float h0 = du[0] * (dg[0] / (1.f + expf(-dg[0])));
                float h1 = du[1] * (dg[1] / (1.f + expf(-dg[1])));
                __nv_bfloat16 h0h, h0l, h1h, h1l;
                split_bf16(h0, h0h, h0l); split_bf16(h1, h1h, h1l);
                *(__nv_bfloat162*)(g_hh + (size_t)e0 * FDIM + colg) = __nv_bfloat162(h0h, h1h);
                *(__nv_bfloat162*)(g_hl + (size_t)e0 * FDIM + colg) = __nv_bfloat162(h0l, h1l);
            }
            if (e1 >= 0) {
                float h0 = du[2] * (dg[2] / (1.f + expf(-dg[2])));
                float h1 = du[3] * (dg[3] / (1.f + expf(-dg[3])));
                __nv_bfloat16 h0h, h0l, h1h, h1l;
                split_bf16(h0, h0h, h0l); split_bf16(h1, h1h, h1l);
                *(__nv_bfloat162*)(g_hh + (size_t)e1 * FDIM + colg) = __nv_bfloat162(h0h, h1h);
                *(__nv_bfloat162*)(g_hl + (size_t)e1 * FDIM + colg) = __nv_bfloat162(h0l, h1l);
            }
        }
    }
}

// ================= Phase B: down warp-MMA GEMM — M64 x N128, warp M32xN32 =================
// Stage: Ah 0, Al 9216 (64 rows x 144B), Bh 18432, Bl 35840 (64 rows x 272B each = 17408).
// Stage = 53248 B; 2 stages + 1KB = 107520 -> 2 blocks/SM.
#define DN_STG  53248
#define DN_SMEM (1024 + 2*DN_STG)

__global__ void __launch_bounds__(256, 2) down_mma_kernel() {
    extern __shared__ char smem[];
    uint32_t sb = smem_u32(smem);
    int e = blockIdx.z;
    int cnt = g_cnt[e];
    int row0 = blockIdx.y * 64;
    if (row0 >= cnt) return;
    int col0 = blockIdx.x * 128;
    int tid = threadIdx.x, wid = tid >> 5, lid = tid & 31;
    int wm = wid >> 2, wn = wid & 3;          // 2 x 4 grid: warp tile M32 x N32
    int g = lid >> 2, t2 = (lid & 3) * 2;
    int*   sTok = (int*)smem;
    float* sW   = (float*)(smem + 256);

    for (int i = tid; i < 64; i += 256) {
        int r = row0 + i;
        sTok[i] = (r < cnt) ? g_list[e * T_TOK + r] : -1;
        sW[i]   = (r < cnt) ? g_wgt [e * T_TOK + r] : 0.f;
    }
    __syncthreads();

    const __nv_bfloat16* dh = g_dh + (size_t)e * FDIM * DIM;   // [F][D]
    const __nv_bfloat16* dl = g_dl + (size_t)e * FDIM * DIM;

    float acc[2][4][4] = {};

    auto stage = [&](int chunk) {
        int kt = chunk * 64;
        uint32_t bb = sb + 1024 + (uint32_t)(chunk & 1) * DN_STG;
        // A hidden hi/lo gathered: 2 arrays x 64 rows x 8 segs = 1024 cp16
#pragma unroll
        for (int it = 0; it < 4; it++) {
            int t = tid + it * 256;
            int arr = t >> 9, u = t & 511, row = u >> 3, seg = u & 7;
            int entry = sTok[row];
            uint32_t bytes = (entry >= 0) ? 16u : 0u;
            const __nv_bfloat16* src = (arr ? g_hl : g_hh)
                + (size_t)((entry >= 0) ? entry : 0) * FDIM + kt + seg * 8;
            cp16(bb + arr * 9216 + row * 144 + seg * 16, src, bytes);
        }
        // B natural [64 K][128 N], row stride 272B: 2 arrays x 64 rows x 16 segs = 2048 cp16
#pragma unroll
        for (int it = 0; it < 8; it++) {
            int t = tid + it * 256;
            int arr = t >> 10, u = t & 1023, row = u >> 4, seg = u & 15;
            const __nv_bfloat16* src = (arr ? dl : dh)
                + (size_t)(kt + row) * DIM + col0 + seg * 8;
            cp16(bb + 18432 + arr * 17408 + row * 272 + seg * 16, src, 16u);
        }
    };

    uint32_t laneA = (uint32_t)(((lid & 7) + ((lid >> 3) & 1) * 8) * 144 + ((lid >> 4) & 1) * 16);
    uint32_t laneB = (uint32_t)(((lid & 7) + ((lid >> 3) & 1) * 8) * 272 + ((lid >> 4) & 1) * 16);

    stage(0); CP_COMMIT();
    for (int c = 0; c < 16; c++) {
        if (c + 1 < 16) { stage(c + 1); CP_COMMIT(); CP_WAITG(1); }
        else            { CP_WAITG(0); }
        __syncthreads();
        uint32_t bb = sb + 1024 + (uint32_t)(c & 1) * DN_STG;
        uint32_t aBase = bb + (uint32_t)(wm * 32) * 144 + laneA;
        uint32_t bBase = bb + 18432 + laneB + (uint32_t)(wn * 32) * 2;
#pragma unroll
        for (int kk = 0; kk < 4; kk++) {
            uint32_t ah[2][4], al[2][4];
#pragma unroll
            for (int mt = 0; mt < 2; mt++) {
                uint32_t aa = aBase + mt * (16 * 144) + kk * 32;
                ldsm_x4(ah[mt], aa);
                ldsm_x4(al[mt], aa + 9216);
            }
#pragma unroll
            for (int nt = 0; nt < 2; nt++) {
                uint32_t ba = bBase + kk * (16 * 272) + nt * 32;
                uint32_t bh[4], bl[4];
                ldsm_x4_t(bh, ba);
                ldsm_x4_t(bl, ba + 17408);
#pragma unroll
                for (int h = 0; h < 2; h++) {
                    int n8 = nt * 2 + h;
#pragma unroll
                    for (int mt = 0; mt < 2; mt++) {
                        mma_bf16(acc[mt][n8], ah[mt], bh + h * 2);
                        mma_bf16(acc[mt][n8], ah[mt], bl + h * 2);
                        mma_bf16(acc[mt][n8], al[mt], bh + h * 2);
                    }
                }
            }
        }
        __syncthreads();
    }

#pragma unroll
    for (int mt = 0; mt < 2; mt++) {
        int r0 = wm * 32 + mt * 16 + g;
        int e0 = sTok[r0], e1 = sTok[r0 + 8];
        float w0 = sW[r0], w1 = sW[r0 + 8];
#pragma unroll
        for (int n8 = 0; n8 < 4; n8++) {
            int cg = col0 + wn * 32 + n8 * 8 + t2;
            const float* d = acc[mt][n8];
            if (e0 >= 0) {
                float2 o = make_float2(w0 * d[0], w0 * d[1]);
                *(float2*)(g_pout + (size_t)e0 * DIM + cg) = o;
            }
            if (e1 >= 0) {
                float2 o = make_float2(w1 * d[2], w1 * d[3]);
                *(float2*)(g_pout + (size_t)e1 * DIM + cg) = o;
            }
        }
    }
}

// ---------------- combine pair slots + aux loss (fused) ----------------
__global__ void combine_kernel(float* __restrict__ out, int out_size) {
    int i = blockIdx.x * blockDim.x + threadIdx.x;
    if (blockIdx.x == 0 && threadIdx.x == 0) {
        float lb = 0.f;
#pragma unroll
        for (int e = 0; e < NE; e++)
            lb += ((float)g_cnt[e] / (float)NPAIR) * (g_sumP[e] / (float)T_TOK);
        out[out_size - 1] = 0.01f * (float)NE * lb + 0.001f * (g_zsum / (float)T_TOK);
    }
    const int N4 = T_TOK * DIM / 4;
    const int D4 = DIM / 4;
    if (i >= N4) return;
    int t = i / D4, c = i % D4;
    const float4* p = (const float4*)g_pout;
    float4 a = p[(size_t)(2 * t) * D4 + c];
    float4 b = p[(size_t)(2 * t + 1) * D4 + c];
    ((float4*)out)[i] = make_float4(a.x + b.x, a.y + b.y, a.z + b.z, a.w + b.w);
}

// ---------------- launch ----------------
extern "C" void kernel_launch(void* const* d_in, const int* in_sizes, int n_in,
                              void* d_out, int out_size) {
    const float* x  = (const float*)d_in[0];
    const float* rw = (const float*)d_in[1];
    const float* gw = (const float*)d_in[2];
    const float* uw = (const float*)d_in[3];
    const float* dw = (const float*)d_in[4];
    float* out = (float*)d_out;

    cudaFuncSetAttribute(gateup_mma_kernel, cudaFuncAttributeMaxDynamicSharedMemorySize, GU_SMEM);
    cudaFuncSetAttribute(down_mma_kernel,   cudaFuncAttributeMaxDynamicSharedMemorySize, DN_SMEM);

    prep_kernel<<<(PREP_TOT + 255) / 256, 256>>>(x, gw, uw, dw);
    router_kernel<<<T_TOK / RT_TOK, 1024>>>(x, rw);
    gateup_mma_kernel<<<dim3(FDIM / 64, T_TOK / 64, NE), 256, GU_SMEM>>>();
    down_mma_kernel<<<dim3(DIM / 128, T_TOK / 64, NE), 256, DN_SMEM>>>();
    combine_kernel<<<(T_TOK * DIM / 4 + 255) / 256, 256>>>(out, out_size);
}